// round 5
// baseline (speedup 1.0000x reference)
#include <cuda_runtime.h>
#include <cstdint>

#define EMBED 1024
#define HEADS 16
#define HDIM  64
#define NBATCH 2
#define SEQ   2048
#define MTOT  (NBATCH * SEQ)   // 4096

// ---------------- scratch (device globals: allocation-free) ----------------
__device__ float g_Q[NBATCH * HEADS * SEQ * HDIM];   // [N,H,L,D]
__device__ float g_K[NBATCH * HEADS * SEQ * HDIM];   // [N,H,L,D]
__device__ float g_V[NBATCH * HEADS * SEQ * HDIM];   // [N,H,D,L]  (transposed)
__device__ float g_AO[MTOT * EMBED];
__device__ float g_xc[MTOT * EMBED];
__device__ float g_wq[EMBED * EMBED];
__device__ float g_wk[EMBED * EMBED];
__device__ float g_wv[EMBED * EMBED];
__device__ float g_wo[EMBED * EMBED];

// ======================= helpers (arch-neutral PTX) =========================
__device__ __forceinline__ float tf32r(float x) {
    uint32_t u;
    asm("cvt.rna.tf32.f32 %0, %1;" : "=r"(u) : "f"(x));
    return __uint_as_float(u);
}
__device__ __forceinline__ float fexp2(float x) {
    float y;
    asm("ex2.approx.ftz.f32 %0, %1;" : "=f"(y) : "f"(x));
    return y;
}
__device__ __forceinline__ uint32_t smem_u32(const void* p) {
    uint32_t a;
    asm("{ .reg .u64 t; cvta.to.shared.u64 t, %1; cvt.u32.u64 %0, t; }"
        : "=r"(a) : "l"(p));
    return a;
}
__device__ __forceinline__ void cp_async16(uint32_t s, const void* g) {
    asm volatile("cp.async.cg.shared.global [%0], [%1], 16;" :: "r"(s), "l"(g));
}
#define CP_COMMIT() asm volatile("cp.async.commit_group;" ::: "memory")
#define CP_WAIT1()  asm volatile("cp.async.wait_group 1;" ::: "memory")

__device__ __forceinline__ void ldm_x4(uint32_t (&r)[4], uint32_t a) {
    asm volatile("ldmatrix.sync.aligned.m8n8.x4.shared.b16 {%0,%1,%2,%3}, [%4];"
                 : "=r"(r[0]), "=r"(r[1]), "=r"(r[2]), "=r"(r[3]) : "r"(a));
}
// d += a(k8) * {b0,b1}
__device__ __forceinline__ void mma_tf32(float (&d)[4], const uint32_t (&a)[4],
                                         uint32_t b0, uint32_t b1) {
    asm volatile("mma.sync.aligned.m16n8k8.row.col.f32.tf32.tf32.f32 "
                 "{%0,%1,%2,%3}, {%4,%5,%6,%7}, {%8,%9}, {%0,%1,%2,%3};"
                 : "+f"(d[0]), "+f"(d[1]), "+f"(d[2]), "+f"(d[3])
                 : "r"(a[0]), "r"(a[1]), "r"(a[2]), "r"(a[3]),
                   "r"(b0), "r"(b1));
}

// ======================= prep: tf32-round x and weights =====================
__global__ void __launch_bounds__(256) prep_cvt(
    const float* __restrict__ x,  const float* __restrict__ wq,
    const float* __restrict__ wk, const float* __restrict__ wv,
    const float* __restrict__ wo)
{
    int t = blockIdx.y;
    const float* src = (t == 0) ? x : (t == 1) ? wq : (t == 2) ? wk
                     : (t == 3) ? wv : wo;
    float* dst = (t == 0) ? g_xc : (t == 1) ? g_wq : (t == 2) ? g_wk
               : (t == 3) ? g_wv : g_wo;
    int n4 = ((t == 0) ? MTOT * EMBED : EMBED * EMBED) / 4;
    for (int i = blockIdx.x * blockDim.x + threadIdx.x; i < n4;
         i += gridDim.x * blockDim.x) {
        float4 v = ((const float4*)src)[i];
        v.x = tf32r(v.x); v.y = tf32r(v.y); v.z = tf32r(v.z); v.w = tf32r(v.w);
        ((float4*)dst)[i] = v;
    }
}

// ======================= tf32 mma GEMM core (128x64xK) ======================
// 3-stage cp.async pipeline, 1 sync/iter. smem/stage: A[128][36]+B[64][36].
#define GA_BYTES 18432                // 128*36*4
#define GSTAGE   27648                // A + B(64*36*4=9216)
#define G_SMEM   82944                // 3 stages

__device__ __forceinline__ void g_load_A(const float* __restrict__ g,
                                         uint32_t s, int k0, int tid) {
#pragma unroll
    for (int t = 0; t < 4; t++) {
        int c = tid + t * 256;        // 0..1023
        int row = c >> 3, ch = c & 7;
        cp_async16(s + (uint32_t)(row * 36 + ch * 4) * 4u,
                   g + row * EMBED + k0 + ch * 4);
    }
}
__device__ __forceinline__ void g_load_B(const float* __restrict__ g,
                                         uint32_t s, int k0, int tid) {
#pragma unroll
    for (int t = 0; t < 2; t++) {
        int c = tid + t * 256;        // 0..511
        int row = c >> 3, ch = c & 7;
        cp_async16(s + (uint32_t)(row * 36 + ch * 4) * 4u,
                   g + row * EMBED + k0 + ch * 4);
    }
}

__device__ __forceinline__ void gemm_core(const float* __restrict__ Ag,
                                          const float* __restrict__ Bg,
                                          uint32_t sbase, int tid,
                                          float acc[2][4][4]) {
    const int w = tid >> 5, l = tid & 31;
    const int wm = (w >> 1) * 32, wn = (w & 1) * 32;
    const uint32_t rowA  = (uint32_t)(wm + ((l >> 3) & 1) * 8 + (l & 7));
    const uint32_t colA  = (uint32_t)((l >> 4) * 4);
    const uint32_t rowB4 = (uint32_t)(wn + (l & 7));
    const uint32_t colB4 = (uint32_t)(((l >> 3) & 3) * 4);

    g_load_A(Ag, sbase, 0, tid);  g_load_B(Bg, sbase + GA_BYTES, 0, tid);
    CP_COMMIT();
    g_load_A(Ag, sbase + GSTAGE, 32, tid);
    g_load_B(Bg, sbase + GSTAGE + GA_BYTES, 32, tid);
    CP_COMMIT();

    for (int i = 0; i < 32; i++) {
        CP_WAIT1();
        __syncthreads();
        if (i + 2 < 32) {
            uint32_t po = (uint32_t)((i + 2) % 3) * GSTAGE;
            g_load_A(Ag, sbase + po, (i + 2) * 32, tid);
            g_load_B(Bg, sbase + po + GA_BYTES, (i + 2) * 32, tid);
        }
        CP_COMMIT();
        uint32_t bo = (uint32_t)(i % 3) * GSTAGE;
        uint32_t ab = sbase + bo, bb = sbase + bo + GA_BYTES;
#pragma unroll
        for (int ks2 = 0; ks2 < 2; ks2++) {
            int kk = ks2 * 16;
            uint32_t a[2][2][4];
#pragma unroll
            for (int mt = 0; mt < 2; mt++)
#pragma unroll
                for (int sl = 0; sl < 2; sl++)
                    ldm_x4(a[mt][sl],
                           ab + ((rowA + mt * 16) * 36 + kk + sl * 8 + colA) * 4);
#pragma unroll
            for (int nt = 0; nt < 4; nt++) {
                uint32_t b[4];
                ldm_x4(b, bb + ((rowB4 + nt * 8) * 36 + kk + colB4) * 4);
#pragma unroll
                for (int mt = 0; mt < 2; mt++) {
                    mma_tf32(acc[mt][nt], a[mt][0], b[0], b[1]);
                    mma_tf32(acc[mt][nt], a[mt][1], b[2], b[3]);
                }
            }
        }
    }
}

// ---------------------------- QKV -------------------------------------------
__global__ void __launch_bounds__(256) qkv_tc()
{
    extern __shared__ char dyn[];
    uint32_t sbase = smem_u32(dyn);
    const int tid = threadIdx.x, w = tid >> 5, l = tid & 31;
    const int row0 = blockIdx.y * 128, col0 = blockIdx.x * 64;
    const float* W = (blockIdx.z == 0) ? g_wq : (blockIdx.z == 1) ? g_wk : g_wv;

    float acc[2][4][4] = {};
    gemm_core(g_xc + row0 * EMBED, W + col0 * EMBED, sbase, tid, acc);

    const int wm = (w >> 1) * 32, wn = (w & 1) * 32;
    const int nb = row0 >> 11;
    const int h  = col0 >> 6;      // col0 is 64-aligned

    if (blockIdx.z < 2) {
        float* dst = (blockIdx.z == 0) ? g_Q : g_K;
#pragma unroll
        for (int mt = 0; mt < 2; mt++) {
            int r  = row0 + wm + mt * 16 + (l >> 2);
            int ll = r & (SEQ - 1);
#pragma unroll
            for (int nt = 0; nt < 4; nt++) {
                int d = wn + nt * 8 + 2 * (l & 3);
                float* p = dst + ((nb * HEADS + h) * SEQ + ll) * HDIM + d;
                *(float2*)p = make_float2(tf32r(acc[mt][nt][0]), tf32r(acc[mt][nt][1]));
                *(float2*)(p + 8 * HDIM) =
                    make_float2(tf32r(acc[mt][nt][2]), tf32r(acc[mt][nt][3]));
            }
        }
    } else {
        // V: transpose in smem -> g_V [N,H,D,L]
        float* ts = (float*)dyn;              // [64 d][132]
        __syncthreads();
#pragma unroll
        for (int mt = 0; mt < 2; mt++) {
            int r = wm + mt * 16 + (l >> 2);
#pragma unroll
            for (int nt = 0; nt < 4; nt++) {
                int cc = wn + nt * 8 + 2 * (l & 3);
                ts[cc * 132 + r]           = tf32r(acc[mt][nt][0]);
                ts[(cc + 1) * 132 + r]     = tf32r(acc[mt][nt][1]);
                ts[cc * 132 + r + 8]       = tf32r(acc[mt][nt][2]);
                ts[(cc + 1) * 132 + r + 8] = tf32r(acc[mt][nt][3]);
            }
        }
        __syncthreads();
        int l0base = row0 & (SEQ - 1);
#pragma unroll
        for (int q = 0; q < 8; q++) {
            int e  = q * 256 + tid;           // 0..2047
            int cc = e >> 5;                  // d 0..63
            int ls = e & 31;
            float4 v = *(const float4*)&ts[cc * 132 + ls * 4];
            *(float4*)(g_V + ((nb * HEADS + h) * HDIM + cc) * SEQ + l0base + ls * 4) = v;
        }
    }
}

// ---------------------------- proj ------------------------------------------
__global__ void __launch_bounds__(256) proj_tc(
    const float* __restrict__ bo, float* __restrict__ out)
{
    extern __shared__ char dyn[];
    uint32_t sbase = smem_u32(dyn);
    const int tid = threadIdx.x, w = tid >> 5, l = tid & 31;
    const int row0 = blockIdx.y * 128, col0 = blockIdx.x * 64;

    float acc[2][4][4] = {};
    gemm_core(g_AO + row0 * EMBED, g_wo + col0 * EMBED, sbase, tid, acc);

    const int wm = (w >> 1) * 32, wn = (w & 1) * 32;
#pragma unroll
    for (int mt = 0; mt < 2; mt++) {
        int r = row0 + wm + mt * 16 + (l >> 2);
#pragma unroll
        for (int nt = 0; nt < 4; nt++) {
            int cc = col0 + wn + nt * 8 + 2 * (l & 3);
            float b0 = bo[cc], b1 = bo[cc + 1];
            *(float2*)(out + r * EMBED + cc) =
                make_float2(acc[mt][nt][0] + b0, acc[mt][nt][1] + b1);
            *(float2*)(out + (r + 8) * EMBED + cc) =
                make_float2(acc[mt][nt][2] + b0, acc[mt][nt][3] + b1);
        }
    }
}

// ======================= flash attention, tf32 mma ==========================
// CTA per (qtile64, head, batch). 4 warps, warp = 16 q rows.
// Qs[64][68], Ps[64][68], K 2x[64][68], V^T 2x[64][68]. 2-stage, 2 sync/iter.
#define A_TILE  17408                 // 64*68*4
#define A_OFF_P A_TILE
#define A_OFF_K (2 * A_TILE)
#define A_OFF_V (4 * A_TILE)
#define A_SMEM  (6 * A_TILE)          // 104448

__device__ __forceinline__ void load_kv(const float* __restrict__ Kg,
                                        const float* __restrict__ Vg,
                                        uint32_t kbuf, uint32_t vbuf,
                                        int kv0, int tid) {
#pragma unroll
    for (int t = 0; t < 8; t++) {
        int c = tid + t * 128;
        int r = c >> 4, ch = c & 15;
        cp_async16(kbuf + (uint32_t)(r * 68 + ch * 4) * 4u,
                   Kg + (kv0 + r) * HDIM + ch * 4);
    }
#pragma unroll
    for (int t = 0; t < 8; t++) {
        int c = tid + t * 128;
        int r = c >> 4, ch = c & 15;   // r = d row of V^T, ch = kv chunk
        cp_async16(vbuf + (uint32_t)(r * 68 + ch * 4) * 4u,
                   Vg + r * SEQ + kv0 + ch * 4);
    }
}

__global__ void __launch_bounds__(128) attn_tc()
{
    extern __shared__ char dyn[];
    uint32_t sb = smem_u32(dyn);
    float* smf = (float*)dyn;
    const int tid = threadIdx.x, w = tid >> 5, l = tid & 31;
    const int qb = blockIdx.x, h = blockIdx.y, nb = blockIdx.z;

    const float* Qg = g_Q + ((nb * HEADS + h) * SEQ + qb * 64) * HDIM;
    const float* Kg = g_K + (nb * HEADS + h) * SEQ * HDIM;
    const float* Vg = g_V + (nb * HEADS + h) * HDIM * SEQ;   // [D][L]

    uint32_t sQ = sb, sP = sb + A_OFF_P, sK = sb + A_OFF_K, sV = sb + A_OFF_V;

    load_kv(Kg, Vg, sK, sV, 0, tid);  CP_COMMIT();
    load_kv(Kg, Vg, sK + A_TILE, sV + A_TILE, 64, tid);  CP_COMMIT();

    // Q load, scaled by log2(e)/32, re-rounded to tf32
    const float qscale = 1.4426950408889634f / 32.0f;
#pragma unroll
    for (int t = 0; t < 8; t++) {
        int c = tid + t * 128;
        int r = c >> 4, ch = c & 15;
        float4 v = *(const float4*)(Qg + r * HDIM + ch * 4);
        v.x = tf32r(v.x * qscale); v.y = tf32r(v.y * qscale);
        v.z = tf32r(v.z * qscale); v.w = tf32r(v.w * qscale);
        *(float4*)(smf + r * 68 + ch * 4) = v;
    }

    const int wm = w * 16;
    const uint32_t rowA  = (uint32_t)(wm + ((l >> 3) & 1) * 8 + (l & 7));
    const uint32_t colA  = (uint32_t)((l >> 4) * 4);
    const uint32_t rowB4 = (uint32_t)(l & 7);
    const uint32_t colB4 = (uint32_t)(((l >> 3) & 3) * 4);

    float o[8][4] = {};
    float mi0 = -1e30f, mi1 = -1e30f, li0 = 0.f, li1 = 0.f;

    for (int it = 0; it < SEQ / 64; it++) {
        CP_WAIT1();
        __syncthreads();
        uint32_t bo = (uint32_t)(it & 1) * A_TILE;
        uint32_t kb = sK + bo, vb = sV + bo;

        // ---- S = Q @ K^T (log2-scaled), paired-k8 B loads ----
        float sv[8][4] = {};
#pragma unroll
        for (int ks2 = 0; ks2 < 4; ks2++) {
            int kk = ks2 * 16;
            uint32_t a0[4], a1[4];
            ldm_x4(a0, sQ + (rowA * 68 + kk + colA) * 4);
            ldm_x4(a1, sQ + (rowA * 68 + kk + 8 + colA) * 4);
#pragma unroll
            for (int nt = 0; nt < 8; nt++) {
                uint32_t b[4];
                ldm_x4(b, kb + ((nt * 8 + rowB4) * 68 + kk + colB4) * 4);
                mma_tf32(sv[nt], a0, b[0], b[1]);
                mma_tf32(sv[nt], a1, b[2], b[3]);
            }
        }

        // ---- online softmax (exp2 domain) ----
        float rm0 = -1e30f, rm1 = -1e30f;
#pragma unroll
        for (int nt = 0; nt < 8; nt++) {
            rm0 = fmaxf(rm0, fmaxf(sv[nt][0], sv[nt][1]));
            rm1 = fmaxf(rm1, fmaxf(sv[nt][2], sv[nt][3]));
        }
#pragma unroll
        for (int off = 1; off <= 2; off <<= 1) {
            rm0 = fmaxf(rm0, __shfl_xor_sync(0xffffffffu, rm0, off));
            rm1 = fmaxf(rm1, __shfl_xor_sync(0xffffffffu, rm1, off));
        }
        float mn0 = fmaxf(mi0, rm0), mn1 = fmaxf(mi1, rm1);
        float c0 = fexp2(mi0 - mn0), c1 = fexp2(mi1 - mn1);
        float rs0 = 0.f, rs1 = 0.f;
        float* Pp = smf + (A_OFF_P >> 2);
        int pr0 = wm + (l >> 2);
#pragma unroll
        for (int nt = 0; nt < 8; nt++) {
            float p0 = tf32r(fexp2(sv[nt][0] - mn0));
            float p1 = tf32r(fexp2(sv[nt][1] - mn0));
            float p2 = tf32r(fexp2(sv[nt][2] - mn1));
            float p3 = tf32r(fexp2(sv[nt][3] - mn1));
            rs0 += p0 + p1;  rs1 += p2 + p3;
            int cc = nt * 8 + 2 * (l & 3);
            *(float2*)(Pp + pr0 * 68 + cc)       = make_float2(p0, p1);
            *(float2*)(Pp + (pr0 + 8) * 68 + cc) = make_float2(p2, p3);
        }
#pragma unroll
        for (int off = 1; off <= 2; off <<= 1) {
            rs0 += __shfl_xor_sync(0xffffffffu, rs0, off);
            rs1 += __shfl_xor_sync(0xffffffffu, rs1, off);
        }
        li0 = li0 * c0 + rs0;  li1 = li1 * c1 + rs1;
        mi0 = mn0;  mi1 = mn1;
#pragma unroll
        for (int dt = 0; dt < 8; dt++) {
            o[dt][0] *= c0; o[dt][1] *= c0; o[dt][2] *= c1; o[dt][3] *= c1;
        }
        __syncwarp();

        // ---- O += P @ V (V^T tiles, paired-k8 B loads) ----
#pragma unroll
        for (int ks2 = 0; ks2 < 4; ks2++) {
            int kk = ks2 * 16;
            uint32_t a0[4], a1[4];
            ldm_x4(a0, sP + (rowA * 68 + kk + colA) * 4);
            ldm_x4(a1, sP + (rowA * 68 + kk + 8 + colA) * 4);
#pragma unroll
            for (int dt = 0; dt < 8; dt++) {
                uint32_t b[4];
                ldm_x4(b, vb + ((dt * 8 + rowB4) * 68 + kk + colB4) * 4);
                mma_tf32(o[dt], a0, b[0], b[1]);
                mma_tf32(o[dt], a1, b[2], b[3]);
            }
        }
        __syncthreads();   // all reads of slot it&1 done before refill
        if (it + 2 < SEQ / 64)
            load_kv(Kg, Vg, sK + bo, sV + bo, (it + 2) * 64, tid);
        CP_COMMIT();
    }

    // epilogue -> g_AO [N,L,E], tf32-rounded (feeds tf32 proj GEMM)
    float inv0 = 1.f / li0, inv1 = 1.f / li1;
    int r0 = qb * 64 + wm + (l >> 2);
    float* Og = g_AO + (nb * SEQ + r0) * EMBED + h * HDIM;
#pragma unroll
    for (int dt = 0; dt < 8; dt++) {
        int cc = dt * 8 + 2 * (l & 3);
        *(float2*)(Og + cc) =
            make_float2(tf32r(o[dt][0] * inv0), tf32r(o[dt][1] * inv0));
        *(float2*)(Og + 8 * EMBED + cc) =
            make_float2(tf32r(o[dt][2] * inv1), tf32r(o[dt][3] * inv1));
    }
}

// ============================================================================
extern "C" void kernel_launch(void* const* d_in, const int* in_sizes, int n_in,
                              void* d_out, int out_size)
{
    const float* x  = (const float*)d_in[0];
    const float* Wq = (const float*)d_in[1];
    const float* Wk = (const float*)d_in[2];
    const float* Wv = (const float*)d_in[3];
    const float* Wo = (const float*)d_in[4];
    const float* bo = (const float*)d_in[5];
    float* out = (float*)d_out;

    cudaFuncSetAttribute(qkv_tc,  cudaFuncAttributeMaxDynamicSharedMemorySize, G_SMEM);
    cudaFuncSetAttribute(proj_tc, cudaFuncAttributeMaxDynamicSharedMemorySize, G_SMEM);
    cudaFuncSetAttribute(attn_tc, cudaFuncAttributeMaxDynamicSharedMemorySize, A_SMEM);
    cudaFuncSetAttribute(qkv_tc,  cudaFuncAttributePreferredSharedMemoryCarveout,
                         cudaSharedmemCarveoutMaxShared);
    cudaFuncSetAttribute(proj_tc, cudaFuncAttributePreferredSharedMemoryCarveout,
                         cudaSharedmemCarveoutMaxShared);
    cudaFuncSetAttribute(attn_tc, cudaFuncAttributePreferredSharedMemoryCarveout,
                         cudaSharedmemCarveoutMaxShared);

    dim3 gp(512, 5);
    prep_cvt<<<gp, 256>>>(x, Wq, Wk, Wv, Wo);

    dim3 g1(EMBED / 64, MTOT / 128, 3);
    qkv_tc<<<g1, 256, G_SMEM>>>();

    dim3 g2(SEQ / 64, HEADS, NBATCH);
    attn_tc<<<g2, 128, A_SMEM>>>();

    dim3 g3(EMBED / 64, MTOT / 128);
    proj_tc<<<g3, 256, G_SMEM>>>(bo, out);
}

// round 9
// speedup vs baseline: 2.3646x; 2.3646x over previous
#include <cuda_runtime.h>
#include <cuda_fp16.h>
#include <cstdint>

#define EMBED 1024
#define HEADS 16
#define HDIM  64
#define NBATCH 2
#define SEQ   2048
#define MTOT  (NBATCH * SEQ)   // 4096

// ---------------- scratch (device globals: allocation-free) ----------------
__device__ __align__(16) __half g_Q[NBATCH * HEADS * SEQ * HDIM];  // [N,H,L,D] prescaled log2e/32
__device__ __align__(16) __half g_K[NBATCH * HEADS * SEQ * HDIM];  // [N,H,L,D]
__device__ __align__(16) __half g_V[NBATCH * HEADS * SEQ * HDIM];  // [N,H,D,L] transposed
__device__ __align__(16) __half g_AO[MTOT * EMBED];                // [N,L,E]
__device__ __align__(16) __half g_xh[MTOT * EMBED];
__device__ __align__(16) __half g_wqh[EMBED * EMBED];
__device__ __align__(16) __half g_wkh[EMBED * EMBED];
__device__ __align__(16) __half g_wvh[EMBED * EMBED];
__device__ __align__(16) __half g_woh[EMBED * EMBED];

// ======================= helpers (arch-neutral PTX) =========================
__device__ __forceinline__ float fexp2(float x) {
    float y;
    asm("ex2.approx.ftz.f32 %0, %1;" : "=f"(y) : "f"(x));
    return y;
}
__device__ __forceinline__ uint32_t smem_u32(const void* p) {
    uint32_t a;
    asm("{ .reg .u64 t; cvta.to.shared.u64 t, %1; cvt.u32.u64 %0, t; }"
        : "=r"(a) : "l"(p));
    return a;
}
__device__ __forceinline__ void cp_async16(uint32_t s, const void* g) {
    asm volatile("cp.async.cg.shared.global [%0], [%1], 16;" :: "r"(s), "l"(g));
}
#define CP_COMMIT() asm volatile("cp.async.commit_group;" ::: "memory")
#define CP_WAIT1()  asm volatile("cp.async.wait_group 1;" ::: "memory")

__device__ __forceinline__ void ldm_x4(uint32_t (&r)[4], uint32_t a) {
    asm volatile("ldmatrix.sync.aligned.m8n8.x4.shared.b16 {%0,%1,%2,%3}, [%4];"
                 : "=r"(r[0]), "=r"(r[1]), "=r"(r[2]), "=r"(r[3]) : "r"(a));
}
// fp16 mma m16n8k16, fp32 accumulate
__device__ __forceinline__ void mma_f16(float (&d)[4], const uint32_t (&a)[4],
                                        uint32_t b0, uint32_t b1) {
    asm volatile("mma.sync.aligned.m16n8k16.row.col.f32.f16.f16.f32 "
                 "{%0,%1,%2,%3}, {%4,%5,%6,%7}, {%8,%9}, {%0,%1,%2,%3};"
                 : "+f"(d[0]), "+f"(d[1]), "+f"(d[2]), "+f"(d[3])
                 : "r"(a[0]), "r"(a[1]), "r"(a[2]), "r"(a[3]),
                   "r"(b0), "r"(b1));
}

// ======================= prep: convert fp32 -> fp16 =========================
__global__ void __launch_bounds__(256) prep_cvt(
    const float* __restrict__ x,  const float* __restrict__ wq,
    const float* __restrict__ wk, const float* __restrict__ wv,
    const float* __restrict__ wo)
{
    int t = blockIdx.y;
    const float* src = (t == 0) ? x : (t == 1) ? wq : (t == 2) ? wk
                     : (t == 3) ? wv : wo;
    __half* dst = (t == 0) ? g_xh : (t == 1) ? g_wqh : (t == 2) ? g_wkh
                : (t == 3) ? g_wvh : g_woh;
    int n4 = ((t == 0) ? MTOT * EMBED : EMBED * EMBED) / 4;
    for (int i = blockIdx.x * blockDim.x + threadIdx.x; i < n4;
         i += gridDim.x * blockDim.x) {
        float4 v = ((const float4*)src)[i];
        __half2 h0 = __floats2half2_rn(v.x, v.y);
        __half2 h1 = __floats2half2_rn(v.z, v.w);
        ((uint2*)dst)[i] = make_uint2(*(uint32_t*)&h0, *(uint32_t*)&h1);
    }
}

// ======================= fp16 mma GEMM core (128x128xK) =====================
// BK=32 halfs (64B/row, padded to 80B). 3-stage cp.async, 1 sync/iter.
// 8 warps: warp tile 64x32 (wm=(w>>2)*64, wn=(w&3)*32).
#define G_RS     80                   // row stride bytes (40 halfs)
#define G_TILEB  10240                // 128 * 80
#define GSTAGE   20480                // A + B
#define G_SMEM   61440                // 3 stages

__device__ __forceinline__ void g_load_tile(const __half* __restrict__ g,
                                            uint32_t s, int k0, int tid) {
#pragma unroll
    for (int t = 0; t < 2; t++) {
        int c = tid + t * 256;        // 0..511
        int row = c >> 2, ch = c & 3;
        cp_async16(s + (uint32_t)(row * G_RS + ch * 16),
                   g + row * EMBED + k0 + ch * 8);
    }
}

__device__ __forceinline__ void gemm_core(const __half* __restrict__ Ag,
                                          const __half* __restrict__ Bg,
                                          uint32_t sbase, int tid,
                                          float acc[4][4][4]) {
    const int w = tid >> 5, l = tid & 31;
    const int wm = (w >> 2) * 64, wn = (w & 3) * 32;
    const uint32_t arow = (uint32_t)(((l >> 3) & 1) * 8 + (l & 7));
    const uint32_t acol = (uint32_t)((l >> 4) * 16);
    const uint32_t brow = (uint32_t)(((l >> 4) & 1) * 8 + (l & 7));
    const uint32_t bcol = (uint32_t)(((l >> 3) & 1) * 16);

    uint32_t sA = sbase, sB = sbase + G_TILEB;
    g_load_tile(Ag, sA, 0, tid);  g_load_tile(Bg, sB, 0, tid);  CP_COMMIT();
    g_load_tile(Ag, sA + GSTAGE, 32, tid);
    g_load_tile(Bg, sB + GSTAGE, 32, tid);  CP_COMMIT();

    for (int i = 0; i < 32; i++) {
        CP_WAIT1();
        __syncthreads();
        if (i + 2 < 32) {
            uint32_t po = (uint32_t)((i + 2) % 3) * GSTAGE;
            g_load_tile(Ag, sA + po, (i + 2) * 32, tid);
            g_load_tile(Bg, sB + po, (i + 2) * 32, tid);
        }
        CP_COMMIT();
        uint32_t bo = (uint32_t)(i % 3) * GSTAGE;
        uint32_t ab = sA + bo, bb = sB + bo;
#pragma unroll
        for (int ks = 0; ks < 2; ks++) {       // two k16 slices per BK=32
            uint32_t kk2 = (uint32_t)(ks * 32);
            uint32_t a[4][4];
#pragma unroll
            for (int mt = 0; mt < 4; mt++)
                ldm_x4(a[mt], ab + (wm + mt * 16 + arow) * G_RS + acol + kk2);
#pragma unroll
            for (int bp = 0; bp < 2; bp++) {
                uint32_t b[4];
                ldm_x4(b, bb + (wn + bp * 16 + brow) * G_RS + bcol + kk2);
#pragma unroll
                for (int mt = 0; mt < 4; mt++) {
                    mma_f16(acc[mt][bp * 2 + 0], a[mt], b[0], b[1]);
                    mma_f16(acc[mt][bp * 2 + 1], a[mt], b[2], b[3]);
                }
            }
        }
    }
}

// ---------------------------- QKV -------------------------------------------
__global__ void __launch_bounds__(256, 2) qkv_tc()
{
    extern __shared__ char dyn[];
    uint32_t sbase = smem_u32(dyn);
    const int tid = threadIdx.x, w = tid >> 5, l = tid & 31;
    const int row0 = blockIdx.y * 128, col0 = blockIdx.x * 128;
    const __half* W = (blockIdx.z == 0) ? g_wqh : (blockIdx.z == 1) ? g_wkh : g_wvh;

    float acc[4][4][4] = {};
    gemm_core(g_xh + row0 * EMBED, W + col0 * EMBED, sbase, tid, acc);

    const int wm = (w >> 2) * 64, wn = (w & 3) * 32;
    const int nb = row0 >> 11;
    const float qscale = 1.4426950408889634f / 32.0f;   // log2(e)/sqrt(E)

    if (blockIdx.z < 2) {
        __half* dst = (blockIdx.z == 0) ? g_Q : g_K;
        float sc = (blockIdx.z == 0) ? qscale : 1.0f;
#pragma unroll
        for (int mt = 0; mt < 4; mt++) {
            int r  = row0 + wm + mt * 16 + (l >> 2);
            int ll = r & (SEQ - 1);
#pragma unroll
            for (int nt = 0; nt < 4; nt++) {
                int cc = col0 + wn + nt * 8 + 2 * (l & 3);
                int h = cc >> 6, d = cc & 63;
                __half* p = dst + ((nb * HEADS + h) * SEQ + ll) * HDIM + d;
                __half2 v0 = __floats2half2_rn(acc[mt][nt][0] * sc, acc[mt][nt][1] * sc);
                __half2 v1 = __floats2half2_rn(acc[mt][nt][2] * sc, acc[mt][nt][3] * sc);
                *(__half2*)p = v0;
                *(__half2*)(p + 8 * HDIM) = v1;
            }
        }
    } else {
        // V: transpose via smem -> g_V [N,H,D,L] fp16
        __half* ts = (__half*)dyn;            // [128 cc][136]
        __syncthreads();
#pragma unroll
        for (int mt = 0; mt < 4; mt++) {
            int r = wm + mt * 16 + (l >> 2);
#pragma unroll
            for (int nt = 0; nt < 4; nt++) {
                int cc = wn + nt * 8 + 2 * (l & 3);
                ts[cc * 136 + r]           = __float2half_rn(acc[mt][nt][0]);
                ts[(cc + 1) * 136 + r]     = __float2half_rn(acc[mt][nt][1]);
                ts[cc * 136 + r + 8]       = __float2half_rn(acc[mt][nt][2]);
                ts[(cc + 1) * 136 + r + 8] = __float2half_rn(acc[mt][nt][3]);
            }
        }
        __syncthreads();
        int l0base = row0 & (SEQ - 1);
#pragma unroll
        for (int q = 0; q < 8; q++) {
            int e  = q * 256 + tid;           // 0..2047
            int cc = e >> 4;                  // 0..127
            int ls = e & 15;
            uint4 v = *(const uint4*)&ts[cc * 136 + ls * 8];
            int gc = col0 + cc;
            int h = gc >> 6, d = gc & 63;
            *(uint4*)(g_V + ((nb * HEADS + h) * HDIM + d) * SEQ + l0base + ls * 8) = v;
        }
    }
}

// ---------------------------- proj ------------------------------------------
__global__ void __launch_bounds__(256, 2) proj_tc(
    const float* __restrict__ bo, float* __restrict__ out)
{
    extern __shared__ char dyn[];
    uint32_t sbase = smem_u32(dyn);
    const int tid = threadIdx.x, w = tid >> 5, l = tid & 31;
    const int row0 = blockIdx.y * 128, col0 = blockIdx.x * 128;

    float acc[4][4][4] = {};
    gemm_core(g_AO + row0 * EMBED, g_woh + col0 * EMBED, sbase, tid, acc);

    const int wm = (w >> 2) * 64, wn = (w & 3) * 32;
#pragma unroll
    for (int mt = 0; mt < 4; mt++) {
        int r = row0 + wm + mt * 16 + (l >> 2);
#pragma unroll
        for (int nt = 0; nt < 4; nt++) {
            int cc = col0 + wn + nt * 8 + 2 * (l & 3);
            float b0 = bo[cc], b1 = bo[cc + 1];
            *(float2*)(out + r * EMBED + cc) =
                make_float2(acc[mt][nt][0] + b0, acc[mt][nt][1] + b1);
            *(float2*)(out + (r + 8) * EMBED + cc) =
                make_float2(acc[mt][nt][2] + b0, acc[mt][nt][3] + b1);
        }
    }
}

// ======================= flash attention, fp16 mma ==========================
// CTA per (qtile128, head, batch). 8 warps, warp = 16 q rows.
// smem (halfs, row stride 72 = 144B): Q[128], P[128], K 2x[64], V^T 2x[64].
#define A_RS    144                   // bytes per row (72 halfs)
#define A_QP    18432                 // 128 * 144
#define A_KV    9216                  // 64 * 144
#define A_OFF_P A_QP
#define A_OFF_K (2 * A_QP)
#define A_OFF_V (2 * A_QP + 2 * A_KV)
#define A_SMEM  (2 * A_QP + 4 * A_KV) // 73728

__device__ __forceinline__ void load_kv(const __half* __restrict__ Kg,
                                        const __half* __restrict__ Vg,
                                        uint32_t kbuf, uint32_t vbuf,
                                        int kv0, int tid) {
#pragma unroll
    for (int t = 0; t < 2; t++) {
        int c = tid + t * 256;        // 0..511
        int r = c >> 3, ch = c & 7;
        cp_async16(kbuf + (uint32_t)(r * A_RS + ch * 16),
                   Kg + (kv0 + r) * HDIM + ch * 8);
    }
#pragma unroll
    for (int t = 0; t < 2; t++) {
        int c = tid + t * 256;
        int r = c >> 3, ch = c & 7;   // r = d row of V^T, ch = kv chunk
        cp_async16(vbuf + (uint32_t)(r * A_RS + ch * 16),
                   Vg + r * SEQ + kv0 + ch * 8);
    }
}

__global__ void __launch_bounds__(256, 2) attn_tc()
{
    extern __shared__ char dyn[];
    uint32_t sb = smem_u32(dyn);
    const int tid = threadIdx.x, w = tid >> 5, l = tid & 31;
    const int qb = blockIdx.x, h = blockIdx.y, nb = blockIdx.z;

    const __half* Qg = g_Q + ((nb * HEADS + h) * SEQ + qb * 128) * HDIM;
    const __half* Kg = g_K + (nb * HEADS + h) * SEQ * HDIM;
    const __half* Vg = g_V + (nb * HEADS + h) * HDIM * SEQ;   // [D][L]

    uint32_t sQ = sb, sP = sb + A_OFF_P, sK = sb + A_OFF_K, sV = sb + A_OFF_V;

    // Q tile FIRST (oldest group => retired by the first wait_group 1)
#pragma unroll
    for (int t = 0; t < 4; t++) {
        int c = tid + t * 256;        // 0..1023
        int r = c >> 3, ch = c & 7;
        cp_async16(sQ + (uint32_t)(r * A_RS + ch * 16),
                   Qg + r * HDIM + ch * 8);
    }
    CP_COMMIT();

    load_kv(Kg, Vg, sK, sV, 0, tid);  CP_COMMIT();
    load_kv(Kg, Vg, sK + A_KV, sV + A_KV, 64, tid);  CP_COMMIT();

    const int wm = w * 16;
    const uint32_t arow = (uint32_t)(((l >> 3) & 1) * 8 + (l & 7));
    const uint32_t acol = (uint32_t)((l >> 4) * 16);
    const uint32_t brow = (uint32_t)(((l >> 4) & 1) * 8 + (l & 7));
    const uint32_t bcol = (uint32_t)(((l >> 3) & 1) * 16);

    float o[8][4] = {};
    float mi0 = -1e30f, mi1 = -1e30f, li0 = 0.f, li1 = 0.f;

    for (int it = 0; it < SEQ / 64; it++) {
        CP_WAIT1();        // it=0: retires Q + kv0 (kv1 may stay in flight)
        __syncthreads();
        uint32_t bo = (uint32_t)(it & 1) * A_KV;
        uint32_t kb = sK + bo, vb = sV + bo;

        // ---- S = Q @ K^T (log2-prescaled Q) ----
        float sv[8][4] = {};
#pragma unroll
        for (int ks = 0; ks < 4; ks++) {       // 4 k16 over HDIM=64
            uint32_t kk2 = (uint32_t)(ks * 32);
            uint32_t a[4];
            ldm_x4(a, sQ + (wm + arow) * A_RS + acol + kk2);
#pragma unroll
            for (int bp = 0; bp < 4; bp++) {   // 8 n8 kv tiles
                uint32_t b[4];
                ldm_x4(b, kb + (bp * 16 + brow) * A_RS + bcol + kk2);
                mma_f16(sv[bp * 2 + 0], a, b[0], b[1]);
                mma_f16(sv[bp * 2 + 1], a, b[2], b[3]);
            }
        }

        // ---- online softmax (exp2 domain) ----
        float rm0 = -1e30f, rm1 = -1e30f;
#pragma unroll
        for (int nt = 0; nt < 8; nt++) {
            rm0 = fmaxf(rm0, fmaxf(sv[nt][0], sv[nt][1]));
            rm1 = fmaxf(rm1, fmaxf(sv[nt][2], sv[nt][3]));
        }
#pragma unroll
        for (int off = 1; off <= 2; off <<= 1) {
            rm0 = fmaxf(rm0, __shfl_xor_sync(0xffffffffu, rm0, off));
            rm1 = fmaxf(rm1, __shfl_xor_sync(0xffffffffu, rm1, off));
        }
        float mn0 = fmaxf(mi0, rm0), mn1 = fmaxf(mi1, rm1);
        float c0 = fexp2(mi0 - mn0), c1 = fexp2(mi1 - mn1);
        float rs0 = 0.f, rs1 = 0.f;
        int pr0 = wm + (l >> 2);
#pragma unroll
        for (int nt = 0; nt < 8; nt++) {
            float p0 = fexp2(sv[nt][0] - mn0);
            float p1 = fexp2(sv[nt][1] - mn0);
            float p2 = fexp2(sv[nt][2] - mn1);
            float p3 = fexp2(sv[nt][3] - mn1);
            rs0 += p0 + p1;  rs1 += p2 + p3;
            int cc = nt * 8 + 2 * (l & 3);
            __half2 h0 = __floats2half2_rn(p0, p1);
            __half2 h1 = __floats2half2_rn(p2, p3);
            *(__half2*)((char*)dyn + (A_OFF_P + pr0 * A_RS + cc * 2)) = h0;
            *(__half2*)((char*)dyn + (A_OFF_P + (pr0 + 8) * A_RS + cc * 2)) = h1;
        }
#pragma unroll
        for (int off = 1; off <= 2; off <<= 1) {
            rs0 += __shfl_xor_sync(0xffffffffu, rs0, off);
            rs1 += __shfl_xor_sync(0xffffffffu, rs1, off);
        }
        li0 = li0 * c0 + rs0;  li1 = li1 * c1 + rs1;
        mi0 = mn0;  mi1 = mn1;
#pragma unroll
        for (int dt = 0; dt < 8; dt++) {
            o[dt][0] *= c0; o[dt][1] *= c0; o[dt][2] *= c1; o[dt][3] *= c1;
        }
        __syncwarp();   // P rows are warp-private

        // ---- O += P @ V ----
#pragma unroll
        for (int ks = 0; ks < 4; ks++) {       // 4 k16 over 64 kv
            uint32_t kk2 = (uint32_t)(ks * 32);
            uint32_t a[4];
            ldm_x4(a, sP + (wm + arow) * A_RS + acol + kk2);
#pragma unroll
            for (int bp = 0; bp < 4; bp++) {   // 8 d8 tiles
                uint32_t b[4];
                ldm_x4(b, vb + (bp * 16 + brow) * A_RS + bcol + kk2);
                mma_f16(o[bp * 2 + 0], a, b[0], b[1]);
                mma_f16(o[bp * 2 + 1], a, b[2], b[3]);
            }
        }
        __syncthreads();   // all reads of slot it&1 done before refill
        if (it + 2 < SEQ / 64)
            load_kv(Kg, Vg, sK + bo, sV + bo, (it + 2) * 64, tid);
        CP_COMMIT();
    }

    // epilogue -> g_AO fp16 [N,L,E]
    float inv0 = 1.f / li0, inv1 = 1.f / li1;
    int r0 = qb * 128 + wm + (l >> 2);
    __half* Og = g_AO + (nb * SEQ + r0) * EMBED + h * HDIM;
#pragma unroll
    for (int dt = 0; dt < 8; dt++) {
        int cc = dt * 8 + 2 * (l & 3);
        __half2 v0 = __floats2half2_rn(o[dt][0] * inv0, o[dt][1] * inv0);
        __half2 v1 = __floats2half2_rn(o[dt][2] * inv1, o[dt][3] * inv1);
        *(__half2*)(Og + cc) = v0;
        *(__half2*)(Og + 8 * EMBED + cc) = v1;
    }
}

// ============================================================================
extern "C" void kernel_launch(void* const* d_in, const int* in_sizes, int n_in,
                              void* d_out, int out_size)
{
    const float* x  = (const float*)d_in[0];
    const float* Wq = (const float*)d_in[1];
    const float* Wk = (const float*)d_in[2];
    const float* Wv = (const float*)d_in[3];
    const float* Wo = (const float*)d_in[4];
    const float* bo = (const float*)d_in[5];
    float* out = (float*)d_out;

    cudaFuncSetAttribute(qkv_tc,  cudaFuncAttributeMaxDynamicSharedMemorySize, G_SMEM);
    cudaFuncSetAttribute(proj_tc, cudaFuncAttributeMaxDynamicSharedMemorySize, G_SMEM);
    cudaFuncSetAttribute(attn_tc, cudaFuncAttributeMaxDynamicSharedMemorySize, A_SMEM);
    cudaFuncSetAttribute(qkv_tc,  cudaFuncAttributePreferredSharedMemoryCarveout,
                         cudaSharedmemCarveoutMaxShared);
    cudaFuncSetAttribute(proj_tc, cudaFuncAttributePreferredSharedMemoryCarveout,
                         cudaSharedmemCarveoutMaxShared);
    cudaFuncSetAttribute(attn_tc, cudaFuncAttributePreferredSharedMemoryCarveout,
                         cudaSharedmemCarveoutMaxShared);

    dim3 gp(512, 5);
    prep_cvt<<<gp, 256>>>(x, Wq, Wk, Wv, Wo);

    dim3 g1(EMBED / 128, MTOT / 128, 3);
    qkv_tc<<<g1, 256, G_SMEM>>>();

    dim3 g2(SEQ / 128, HEADS, NBATCH);
    attn_tc<<<g2, 256, A_SMEM>>>();

    dim3 g3(EMBED / 128, MTOT / 128);
    proj_tc<<<g3, 256, G_SMEM>>>(bo, out);
}

// round 10
// speedup vs baseline: 2.4815x; 1.0494x over previous
#include <cuda_runtime.h>
#include <cuda_fp16.h>
#include <cstdint>

#define EMBED 1024
#define HEADS 16
#define HDIM  64
#define NBATCH 2
#define SEQ   2048
#define MTOT  (NBATCH * SEQ)   // 4096

// ---------------- scratch (device globals: allocation-free) ----------------
__device__ __align__(16) __half g_Q[NBATCH * HEADS * SEQ * HDIM];  // [N,H,L,D] prescaled log2e/32
__device__ __align__(16) __half g_K[NBATCH * HEADS * SEQ * HDIM];  // [N,H,L,D]
__device__ __align__(16) __half g_V[NBATCH * HEADS * SEQ * HDIM];  // [N,H,D,L] transposed
__device__ __align__(16) __half g_AO[MTOT * EMBED];                // [N,L,E]
__device__ __align__(16) __half g_xh[MTOT * EMBED];
__device__ __align__(16) __half g_wqh[EMBED * EMBED];
__device__ __align__(16) __half g_wkh[EMBED * EMBED];
__device__ __align__(16) __half g_wvh[EMBED * EMBED];
__device__ __align__(16) __half g_woh[EMBED * EMBED];

// ======================= helpers (arch-neutral PTX) =========================
__device__ __forceinline__ float fexp2(float x) {
    float y;
    asm("ex2.approx.ftz.f32 %0, %1;" : "=f"(y) : "f"(x));
    return y;
}
__device__ __forceinline__ uint32_t smem_u32(const void* p) {
    uint32_t a;
    asm("{ .reg .u64 t; cvta.to.shared.u64 t, %1; cvt.u32.u64 %0, t; }"
        : "=r"(a) : "l"(p));
    return a;
}
__device__ __forceinline__ void cp_async16(uint32_t s, const void* g) {
    asm volatile("cp.async.cg.shared.global [%0], [%1], 16;" :: "r"(s), "l"(g));
}
#define CP_COMMIT() asm volatile("cp.async.commit_group;" ::: "memory")
#define CP_WAIT1()  asm volatile("cp.async.wait_group 1;" ::: "memory")
#define CP_WAIT2()  asm volatile("cp.async.wait_group 2;" ::: "memory")

__device__ __forceinline__ void ldm_x4(uint32_t (&r)[4], uint32_t a) {
    asm volatile("ldmatrix.sync.aligned.m8n8.x4.shared.b16 {%0,%1,%2,%3}, [%4];"
                 : "=r"(r[0]), "=r"(r[1]), "=r"(r[2]), "=r"(r[3]) : "r"(a));
}
// fp16 mma m16n8k16, fp32 accumulate
__device__ __forceinline__ void mma_f16(float (&d)[4], const uint32_t (&a)[4],
                                        uint32_t b0, uint32_t b1) {
    asm volatile("mma.sync.aligned.m16n8k16.row.col.f32.f16.f16.f32 "
                 "{%0,%1,%2,%3}, {%4,%5,%6,%7}, {%8,%9}, {%0,%1,%2,%3};"
                 : "+f"(d[0]), "+f"(d[1]), "+f"(d[2]), "+f"(d[3])
                 : "r"(a[0]), "r"(a[1]), "r"(a[2]), "r"(a[3]),
                   "r"(b0), "r"(b1));
}
__device__ __forceinline__ uint32_t h2pack(float a, float b) {
    __half2 h = __floats2half2_rn(a, b);
    return *(uint32_t*)&h;
}

// ======================= prep: convert fp32 -> fp16 =========================
__global__ void __launch_bounds__(256) prep_cvt(
    const float* __restrict__ x,  const float* __restrict__ wq,
    const float* __restrict__ wk, const float* __restrict__ wv,
    const float* __restrict__ wo)
{
    int t = blockIdx.y;
    const float* src = (t == 0) ? x : (t == 1) ? wq : (t == 2) ? wk
                     : (t == 3) ? wv : wo;
    __half* dst = (t == 0) ? g_xh : (t == 1) ? g_wqh : (t == 2) ? g_wkh
                : (t == 3) ? g_wvh : g_woh;
    int n4 = ((t == 0) ? MTOT * EMBED : EMBED * EMBED) / 4;
    for (int i = blockIdx.x * blockDim.x + threadIdx.x; i < n4;
         i += gridDim.x * blockDim.x) {
        float4 v = ((const float4*)src)[i];
        __half2 h0 = __floats2half2_rn(v.x, v.y);
        __half2 h1 = __floats2half2_rn(v.z, v.w);
        ((uint2*)dst)[i] = make_uint2(*(uint32_t*)&h0, *(uint32_t*)&h1);
    }
}

// ======================= fp16 mma GEMM core (128x128xK) =====================
// BK=32 halfs (64B/row, padded to 80B). 3-stage cp.async, 1 sync/iter.
#define G_RS     80
#define G_TILEB  10240
#define GSTAGE   20480
#define G_SMEM   61440

__device__ __forceinline__ void g_load_tile(const __half* __restrict__ g,
                                            uint32_t s, int k0, int tid) {
#pragma unroll
    for (int t = 0; t < 2; t++) {
        int c = tid + t * 256;
        int row = c >> 2, ch = c & 3;
        cp_async16(s + (uint32_t)(row * G_RS + ch * 16),
                   g + row * EMBED + k0 + ch * 8);
    }
}

__device__ __forceinline__ void gemm_core(const __half* __restrict__ Ag,
                                          const __half* __restrict__ Bg,
                                          uint32_t sbase, int tid,
                                          float acc[4][4][4]) {
    const int w = tid >> 5, l = tid & 31;
    const int wm = (w >> 2) * 64, wn = (w & 3) * 32;
    const uint32_t arow = (uint32_t)(((l >> 3) & 1) * 8 + (l & 7));
    const uint32_t acol = (uint32_t)((l >> 4) * 16);
    const uint32_t brow = (uint32_t)(((l >> 4) & 1) * 8 + (l & 7));
    const uint32_t bcol = (uint32_t)(((l >> 3) & 1) * 16);

    uint32_t sA = sbase, sB = sbase + G_TILEB;
    g_load_tile(Ag, sA, 0, tid);  g_load_tile(Bg, sB, 0, tid);  CP_COMMIT();
    g_load_tile(Ag, sA + GSTAGE, 32, tid);
    g_load_tile(Bg, sB + GSTAGE, 32, tid);  CP_COMMIT();

    for (int i = 0; i < 32; i++) {
        CP_WAIT1();
        __syncthreads();
        if (i + 2 < 32) {
            uint32_t po = (uint32_t)((i + 2) % 3) * GSTAGE;
            g_load_tile(Ag, sA + po, (i + 2) * 32, tid);
            g_load_tile(Bg, sB + po, (i + 2) * 32, tid);
        }
        CP_COMMIT();
        uint32_t bo = (uint32_t)(i % 3) * GSTAGE;
        uint32_t ab = sA + bo, bb = sB + bo;
#pragma unroll
        for (int ks = 0; ks < 2; ks++) {
            uint32_t kk2 = (uint32_t)(ks * 32);
            uint32_t a[4][4];
#pragma unroll
            for (int mt = 0; mt < 4; mt++)
                ldm_x4(a[mt], ab + (wm + mt * 16 + arow) * G_RS + acol + kk2);
#pragma unroll
            for (int bp = 0; bp < 2; bp++) {
                uint32_t b[4];
                ldm_x4(b, bb + (wn + bp * 16 + brow) * G_RS + bcol + kk2);
#pragma unroll
                for (int mt = 0; mt < 4; mt++) {
                    mma_f16(acc[mt][bp * 2 + 0], a[mt], b[0], b[1]);
                    mma_f16(acc[mt][bp * 2 + 1], a[mt], b[2], b[3]);
                }
            }
        }
    }
}

// ---------------------------- QKV -------------------------------------------
__global__ void __launch_bounds__(256, 2) qkv_tc()
{
    extern __shared__ char dyn[];
    uint32_t sbase = smem_u32(dyn);
    const int tid = threadIdx.x, w = tid >> 5, l = tid & 31;
    const int row0 = blockIdx.y * 128, col0 = blockIdx.x * 128;
    const __half* W = (blockIdx.z == 0) ? g_wqh : (blockIdx.z == 1) ? g_wkh : g_wvh;

    float acc[4][4][4] = {};
    gemm_core(g_xh + row0 * EMBED, W + col0 * EMBED, sbase, tid, acc);

    const int wm = (w >> 2) * 64, wn = (w & 3) * 32;
    const int nb = row0 >> 11;
    const float qscale = 1.4426950408889634f / 32.0f;   // log2(e)/sqrt(E)

    if (blockIdx.z < 2) {
        __half* dst = (blockIdx.z == 0) ? g_Q : g_K;
        float sc = (blockIdx.z == 0) ? qscale : 1.0f;
#pragma unroll
        for (int mt = 0; mt < 4; mt++) {
            int r  = row0 + wm + mt * 16 + (l >> 2);
            int ll = r & (SEQ - 1);
#pragma unroll
            for (int nt = 0; nt < 4; nt++) {
                int cc = col0 + wn + nt * 8 + 2 * (l & 3);
                int h = cc >> 6, d = cc & 63;
                __half* p = dst + ((nb * HEADS + h) * SEQ + ll) * HDIM + d;
                __half2 v0 = __floats2half2_rn(acc[mt][nt][0] * sc, acc[mt][nt][1] * sc);
                __half2 v1 = __floats2half2_rn(acc[mt][nt][2] * sc, acc[mt][nt][3] * sc);
                *(__half2*)p = v0;
                *(__half2*)(p + 8 * HDIM) = v1;
            }
        }
    } else {
        // V: transpose via smem -> g_V [N,H,D,L] fp16
        __half* ts = (__half*)dyn;            // [128 cc][136]
        __syncthreads();
#pragma unroll
        for (int mt = 0; mt < 4; mt++) {
            int r = wm + mt * 16 + (l >> 2);
#pragma unroll
            for (int nt = 0; nt < 4; nt++) {
                int cc = wn + nt * 8 + 2 * (l & 3);
                ts[cc * 136 + r]           = __float2half_rn(acc[mt][nt][0]);
                ts[(cc + 1) * 136 + r]     = __float2half_rn(acc[mt][nt][1]);
                ts[cc * 136 + r + 8]       = __float2half_rn(acc[mt][nt][2]);
                ts[(cc + 1) * 136 + r + 8] = __float2half_rn(acc[mt][nt][3]);
            }
        }
        __syncthreads();
        int l0base = row0 & (SEQ - 1);
#pragma unroll
        for (int q = 0; q < 8; q++) {
            int e  = q * 256 + tid;
            int cc = e >> 4;
            int ls = e & 15;
            uint4 v = *(const uint4*)&ts[cc * 136 + ls * 8];
            int gc = col0 + cc;
            int h = gc >> 6, d = gc & 63;
            *(uint4*)(g_V + ((nb * HEADS + h) * HDIM + d) * SEQ + l0base + ls * 8) = v;
        }
    }
}

// ---------------------------- proj ------------------------------------------
__global__ void __launch_bounds__(256, 2) proj_tc(
    const float* __restrict__ bo, float* __restrict__ out)
{
    extern __shared__ char dyn[];
    uint32_t sbase = smem_u32(dyn);
    const int tid = threadIdx.x, w = tid >> 5, l = tid & 31;
    const int row0 = blockIdx.y * 128, col0 = blockIdx.x * 128;

    float acc[4][4][4] = {};
    gemm_core(g_AO + row0 * EMBED, g_woh + col0 * EMBED, sbase, tid, acc);

    const int wm = (w >> 2) * 64, wn = (w & 3) * 32;
#pragma unroll
    for (int mt = 0; mt < 4; mt++) {
        int r = row0 + wm + mt * 16 + (l >> 2);
#pragma unroll
        for (int nt = 0; nt < 4; nt++) {
            int cc = col0 + wn + nt * 8 + 2 * (l & 3);
            float b0 = bo[cc], b1 = bo[cc + 1];
            *(float2*)(out + r * EMBED + cc) =
                make_float2(acc[mt][nt][0] + b0, acc[mt][nt][1] + b1);
            *(float2*)(out + (r + 8) * EMBED + cc) =
                make_float2(acc[mt][nt][2] + b0, acc[mt][nt][3] + b1);
        }
    }
}

// ======================= flash attention, fp16 mma ==========================
// CTA per (qtile128, head, batch). 8 warps, warp = 16 q rows.
// P never touches smem: S-accumulator fragments repack directly into PV
// A-operands (m16n8k16 C-layout == A-layout identity, FA2 style).
// smem: Q[128][72h], K 3x[64][72h], V^T 3x[64][72h]. 3-stage, 1 sync/iter.
#define A_RS    144                   // bytes per row (72 halfs)
#define A_QP    18432                 // 128 * 144
#define A_KV    9216                  // 64 * 144
#define A_OFF_K A_QP
#define A_OFF_V (A_QP + 3 * A_KV)
#define A_SMEM  (A_QP + 6 * A_KV)     // 73728

__device__ __forceinline__ void load_kv(const __half* __restrict__ Kg,
                                        const __half* __restrict__ Vg,
                                        uint32_t kbuf, uint32_t vbuf,
                                        int kv0, int tid) {
#pragma unroll
    for (int t = 0; t < 2; t++) {
        int c = tid + t * 256;
        int r = c >> 3, ch = c & 7;
        cp_async16(kbuf + (uint32_t)(r * A_RS + ch * 16),
                   Kg + (kv0 + r) * HDIM + ch * 8);
    }
#pragma unroll
    for (int t = 0; t < 2; t++) {
        int c = tid + t * 256;
        int r = c >> 3, ch = c & 7;   // r = d row of V^T
        cp_async16(vbuf + (uint32_t)(r * A_RS + ch * 16),
                   Vg + r * SEQ + kv0 + ch * 8);
    }
}

__global__ void __launch_bounds__(256, 2) attn_tc()
{
    extern __shared__ char dyn[];
    uint32_t sb = smem_u32(dyn);
    const int tid = threadIdx.x, w = tid >> 5, l = tid & 31;
    const int qb = blockIdx.x, h = blockIdx.y, nb = blockIdx.z;

    const __half* Qg = g_Q + ((nb * HEADS + h) * SEQ + qb * 128) * HDIM;
    const __half* Kg = g_K + (nb * HEADS + h) * SEQ * HDIM;
    const __half* Vg = g_V + (nb * HEADS + h) * HDIM * SEQ;   // [D][L]

    uint32_t sQ = sb, sK = sb + A_OFF_K, sV = sb + A_OFF_V;

    // Q tile FIRST (oldest cp.async group)
#pragma unroll
    for (int t = 0; t < 4; t++) {
        int c = tid + t * 256;
        int r = c >> 3, ch = c & 7;
        cp_async16(sQ + (uint32_t)(r * A_RS + ch * 16),
                   Qg + r * HDIM + ch * 8);
    }
    CP_COMMIT();
    load_kv(Kg, Vg, sK, sV, 0, tid);  CP_COMMIT();
    load_kv(Kg, Vg, sK + A_KV, sV + A_KV, 64, tid);  CP_COMMIT();

    const int wm = w * 16;
    const uint32_t arow = (uint32_t)(((l >> 3) & 1) * 8 + (l & 7));
    const uint32_t acol = (uint32_t)((l >> 4) * 16);
    const uint32_t brow = (uint32_t)(((l >> 4) & 1) * 8 + (l & 7));
    const uint32_t bcol = (uint32_t)(((l >> 3) & 1) * 16);

    // hoist Q fragments (loop-invariant)
    CP_WAIT2();          // Q group retired
    __syncthreads();     // cross-warp visibility of Q tile
    uint32_t qf[4][4];
#pragma unroll
    for (int ks = 0; ks < 4; ks++)
        ldm_x4(qf[ks], sQ + (wm + arow) * A_RS + acol + (uint32_t)(ks * 32));

    float o[8][4] = {};
    float mi0 = -1e30f, mi1 = -1e30f, li0 = 0.f, li1 = 0.f;

    const int NIT = SEQ / 64;
    for (int it = 0; it < NIT; it++) {
        CP_WAIT1();
        __syncthreads();
        if (it + 2 < NIT) {
            uint32_t po = (uint32_t)((it + 2) % 3) * A_KV;
            load_kv(Kg, Vg, sK + po, sV + po, (it + 2) * 64, tid);
        }
        CP_COMMIT();
        uint32_t bo = (uint32_t)(it % 3) * A_KV;
        uint32_t kb = sK + bo, vb = sV + bo;

        // ---- S = Q @ K^T (Q frags in regs) ----
        float sv[8][4] = {};
#pragma unroll
        for (int ks = 0; ks < 4; ks++) {
            uint32_t kk2 = (uint32_t)(ks * 32);
#pragma unroll
            for (int bp = 0; bp < 4; bp++) {
                uint32_t b[4];
                ldm_x4(b, kb + (bp * 16 + brow) * A_RS + bcol + kk2);
                mma_f16(sv[bp * 2 + 0], qf[ks], b[0], b[1]);
                mma_f16(sv[bp * 2 + 1], qf[ks], b[2], b[3]);
            }
        }

        // ---- online softmax; pack P into PV A-fragments (no smem) ----
        float rm0 = -1e30f, rm1 = -1e30f;
#pragma unroll
        for (int nt = 0; nt < 8; nt++) {
            rm0 = fmaxf(rm0, fmaxf(sv[nt][0], sv[nt][1]));
            rm1 = fmaxf(rm1, fmaxf(sv[nt][2], sv[nt][3]));
        }
#pragma unroll
        for (int off = 1; off <= 2; off <<= 1) {
            rm0 = fmaxf(rm0, __shfl_xor_sync(0xffffffffu, rm0, off));
            rm1 = fmaxf(rm1, __shfl_xor_sync(0xffffffffu, rm1, off));
        }
        float mn0 = fmaxf(mi0, rm0), mn1 = fmaxf(mi1, rm1);
        float c0 = fexp2(mi0 - mn0), c1 = fexp2(mi1 - mn1);
        float rs0 = 0.f, rs1 = 0.f;
        uint32_t pa[4][4];
#pragma unroll
        for (int ks = 0; ks < 4; ks++) {
            float e00 = fexp2(sv[2*ks][0] - mn0),   e01 = fexp2(sv[2*ks][1] - mn0);
            float e02 = fexp2(sv[2*ks][2] - mn1),   e03 = fexp2(sv[2*ks][3] - mn1);
            float e10 = fexp2(sv[2*ks+1][0] - mn0), e11 = fexp2(sv[2*ks+1][1] - mn0);
            float e12 = fexp2(sv[2*ks+1][2] - mn1), e13 = fexp2(sv[2*ks+1][3] - mn1);
            rs0 += (e00 + e01) + (e10 + e11);
            rs1 += (e02 + e03) + (e12 + e13);
            pa[ks][0] = h2pack(e00, e01);   // (row g,   k 2t..2t+1)
            pa[ks][1] = h2pack(e02, e03);   // (row g+8, k 2t..2t+1)
            pa[ks][2] = h2pack(e10, e11);   // (row g,   k 8+2t..)
            pa[ks][3] = h2pack(e12, e13);   // (row g+8, k 8+2t..)
        }
#pragma unroll
        for (int off = 1; off <= 2; off <<= 1) {
            rs0 += __shfl_xor_sync(0xffffffffu, rs0, off);
            rs1 += __shfl_xor_sync(0xffffffffu, rs1, off);
        }
        li0 = li0 * c0 + rs0;  li1 = li1 * c1 + rs1;
        mi0 = mn0;  mi1 = mn1;
#pragma unroll
        for (int dt = 0; dt < 8; dt++) {
            o[dt][0] *= c0; o[dt][1] *= c0; o[dt][2] *= c1; o[dt][3] *= c1;
        }

        // ---- O += P @ V (P from registers) ----
#pragma unroll
        for (int ks = 0; ks < 4; ks++) {
            uint32_t kk2 = (uint32_t)(ks * 32);
#pragma unroll
            for (int bp = 0; bp < 4; bp++) {
                uint32_t b[4];
                ldm_x4(b, vb + (bp * 16 + brow) * A_RS + bcol + kk2);
                mma_f16(o[bp * 2 + 0], pa[ks], b[0], b[1]);
                mma_f16(o[bp * 2 + 1], pa[ks], b[2], b[3]);
            }
        }
    }

    // epilogue -> g_AO fp16 [N,L,E]
    float inv0 = 1.f / li0, inv1 = 1.f / li1;
    int r0 = qb * 128 + wm + (l >> 2);
    __half* Og = g_AO + (nb * SEQ + r0) * EMBED + h * HDIM;
#pragma unroll
    for (int dt = 0; dt < 8; dt++) {
        int cc = dt * 8 + 2 * (l & 3);
        __half2 v0 = __floats2half2_rn(o[dt][0] * inv0, o[dt][1] * inv0);
        __half2 v1 = __floats2half2_rn(o[dt][2] * inv1, o[dt][3] * inv1);
        *(__half2*)(Og + cc) = v0;
        *(__half2*)(Og + 8 * EMBED + cc) = v1;
    }
}

// ============================================================================
extern "C" void kernel_launch(void* const* d_in, const int* in_sizes, int n_in,
                              void* d_out, int out_size)
{
    const float* x  = (const float*)d_in[0];
    const float* Wq = (const float*)d_in[1];
    const float* Wk = (const float*)d_in[2];
    const float* Wv = (const float*)d_in[3];
    const float* Wo = (const float*)d_in[4];
    const float* bo = (const float*)d_in[5];
    float* out = (float*)d_out;

    cudaFuncSetAttribute(qkv_tc,  cudaFuncAttributeMaxDynamicSharedMemorySize, G_SMEM);
    cudaFuncSetAttribute(proj_tc, cudaFuncAttributeMaxDynamicSharedMemorySize, G_SMEM);
    cudaFuncSetAttribute(attn_tc, cudaFuncAttributeMaxDynamicSharedMemorySize, A_SMEM);
    cudaFuncSetAttribute(qkv_tc,  cudaFuncAttributePreferredSharedMemoryCarveout,
                         cudaSharedmemCarveoutMaxShared);
    cudaFuncSetAttribute(proj_tc, cudaFuncAttributePreferredSharedMemoryCarveout,
                         cudaSharedmemCarveoutMaxShared);
    cudaFuncSetAttribute(attn_tc, cudaFuncAttributePreferredSharedMemoryCarveout,
                         cudaSharedmemCarveoutMaxShared);

    dim3 gp(512, 5);
    prep_cvt<<<gp, 256>>>(x, Wq, Wk, Wv, Wo);

    dim3 g1(EMBED / 128, MTOT / 128, 3);
    qkv_tc<<<g1, 256, G_SMEM>>>();

    dim3 g2(SEQ / 128, HEADS, NBATCH);
    attn_tc<<<g2, 256, A_SMEM>>>();

    dim3 g3(EMBED / 128, MTOT / 128);
    proj_tc<<<g3, 256, G_SMEM>>>(bo, out);
}